// round 9
// baseline (speedup 1.0000x reference)
#include <cuda_runtime.h>
#include <cstdint>
#include <cstddef>

#define NNODES 100000
#define NEDGES 20000
#define D 128

// ---- scratch (device globals: allocation-free) ----
__device__ __align__(16) float g_y[(size_t)NNODES * D];      // x @ conv_W
__device__ __align__(16) float g_efeat[(size_t)NEDGES * D];  // hyperedge accum
__device__ int   g_degn[NNODES];
__device__ int   g_dege[NEDGES];
__device__ float g_invn[NNODES];
__device__ float g_inve[NEDGES];

// ---- zero e_feat + degree counters ----
__global__ __launch_bounds__(256) void k_zero() {
    int i = blockIdx.x * blockDim.x + threadIdx.x;
    const int nef4 = (NEDGES * D) / 4;  // 640000 float4
    if (i < nef4) {
        ((float4*)g_efeat)[i] = make_float4(0.f, 0.f, 0.f, 0.f);
    }
    if (i < NNODES) g_degn[i] = 0;
    if (i < NEDGES) g_dege[i] = 0;
}

// ---- degree counts ----
__global__ __launch_bounds__(256) void k_degree(const int* __restrict__ ni,
                                                const int* __restrict__ ei, int nnz) {
    int i = blockIdx.x * blockDim.x + threadIdx.x;
    if (i < nnz) {
        atomicAdd(&g_degn[ni[i]], 1);
        atomicAdd(&g_dege[ei[i]], 1);
    }
}

// ---- 1/deg ----
__global__ __launch_bounds__(256) void k_inv() {
    int i = blockIdx.x * blockDim.x + threadIdx.x;
    if (i < NNODES) {
        int d = g_degn[i];
        g_invn[i] = d > 0 ? 1.0f / (float)d : 0.0f;
    }
    if (i < NEDGES) {
        int d = g_dege[i];
        g_inve[i] = d > 0 ? 1.0f / (float)d : 0.0f;
    }
}

// ---- fp32 GEMM: C[M,128] = A[M,128] @ B[128,128] (+ bias1 + bias2) ----
// Block tile 64x128, 256 threads, thread tile 8x4, BK=8.
__global__ __launch_bounds__(256) void k_gemm(const float* __restrict__ A,
                                              const float* __restrict__ B,
                                              const float* __restrict__ bias1,
                                              const float* __restrict__ bias2,
                                              float* __restrict__ C, int M) {
    __shared__ float As[8][64];   // [k][m] so a-frag is LDS.128 broadcast
    __shared__ float Bs[8][128];

    const int t   = threadIdx.x;
    const int tx  = t & 31;        // n micro-tile (4 cols)
    const int ty  = t >> 5;        // m micro-tile (8 rows)
    const int row0 = blockIdx.x * 64;

    // A-load mapping: 64 rows x 8 k per iter; each thread one float2 along k
    const int tm  = t & 63;
    const int tk2 = (t >> 6) * 2;  // 0,2,4,6
    int arow = row0 + tm;
    if (arow >= M) arow = M - 1;   // clamp; epilogue guards writes
    const float* Aptr = A + (size_t)arow * D + tk2;

    // B-load mapping: 8 rows x 128; each thread one float4
    const int kb = t >> 5;
    const int nb = (t & 31) * 4;

    float acc[8][4];
#pragma unroll
    for (int i = 0; i < 8; i++)
#pragma unroll
        for (int j = 0; j < 4; j++) acc[i][j] = 0.f;

    for (int kk = 0; kk < D; kk += 8) {
        float2 a2 = *(const float2*)(Aptr + kk);
        As[tk2][tm]     = a2.x;
        As[tk2 + 1][tm] = a2.y;
        *(float4*)&Bs[kb][nb] = *(const float4*)&B[(size_t)(kk + kb) * D + nb];
        __syncthreads();
#pragma unroll
        for (int k = 0; k < 8; k++) {
            float4 b4 = *(const float4*)&Bs[k][tx * 4];
            float4 a0 = *(const float4*)&As[k][ty * 8];
            float4 a1 = *(const float4*)&As[k][ty * 8 + 4];
            float a[8] = {a0.x, a0.y, a0.z, a0.w, a1.x, a1.y, a1.z, a1.w};
#pragma unroll
            for (int i = 0; i < 8; i++) {
                acc[i][0] += a[i] * b4.x;
                acc[i][1] += a[i] * b4.y;
                acc[i][2] += a[i] * b4.z;
                acc[i][3] += a[i] * b4.w;
            }
        }
        __syncthreads();
    }

    float4 bias = make_float4(0.f, 0.f, 0.f, 0.f);
    if (bias1) {
        float4 b = *(const float4*)&bias1[tx * 4];
        bias.x += b.x; bias.y += b.y; bias.z += b.z; bias.w += b.w;
    }
    if (bias2) {
        float4 b = *(const float4*)&bias2[tx * 4];
        bias.x += b.x; bias.y += b.y; bias.z += b.z; bias.w += b.w;
    }
#pragma unroll
    for (int i = 0; i < 8; i++) {
        int row = row0 + ty * 8 + i;
        if (row < M) {
            float4 o = make_float4(acc[i][0] + bias.x, acc[i][1] + bias.y,
                                   acc[i][2] + bias.z, acc[i][3] + bias.w);
            *(float4*)&C[(size_t)row * D + tx * 4] = o;
        }
    }
}

__device__ __forceinline__ void red_add_v4(float* p, float4 v) {
    asm volatile("red.global.add.v4.f32 [%0], {%1, %2, %3, %4};"
                 :: "l"(p), "f"(v.x), "f"(v.y), "f"(v.z), "f"(v.w)
                 : "memory");
}

// ---- pass 1: e_feat[edge] += y[node]  (one warp per nz, float4/lane) ----
__global__ __launch_bounds__(256) void k_scatter_edge(const int* __restrict__ ni,
                                                      const int* __restrict__ ei, int nnz) {
    int w = blockIdx.x * 8 + (threadIdx.x >> 5);
    int lane = threadIdx.x & 31;
    if (w >= nnz) return;
    int node = __ldg(&ni[w]);
    int edge = __ldg(&ei[w]);
    float4 v = *(const float4*)&g_y[(size_t)node * D + lane * 4];
    red_add_v4(&g_efeat[(size_t)edge * D + lane * 4], v);
}

// ---- pass 2: out[node] += e_feat[edge] * inv_e[edge] * inv_n[node] ----
__global__ __launch_bounds__(256) void k_scatter_node(const int* __restrict__ ni,
                                                      const int* __restrict__ ei,
                                                      float* __restrict__ out, int nnz) {
    int w = blockIdx.x * 8 + (threadIdx.x >> 5);
    int lane = threadIdx.x & 31;
    if (w >= nnz) return;
    int node = __ldg(&ni[w]);
    int edge = __ldg(&ei[w]);
    float s = g_inve[edge] * g_invn[node];
    float4 v = *(const float4*)&g_efeat[(size_t)edge * D + lane * 4];
    v.x *= s; v.y *= s; v.z *= s; v.w *= s;
    red_add_v4(&out[(size_t)node * D + lane * 4], v);
}

extern "C" void kernel_launch(void* const* d_in, const int* in_sizes, int n_in,
                              void* d_out, int out_size) {
    const float* x      = (const float*)d_in[0];
    const int*   ni     = (const int*)d_in[1];
    const int*   ei     = (const int*)d_in[2];
    const float* conv_W = (const float*)d_in[3];
    const float* conv_b = (const float*)d_in[4];
    const float* res_W  = (const float*)d_in[5];
    const float* res_b  = (const float*)d_in[6];
    float* out = (float*)d_out;

    const int M   = in_sizes[0] / D;   // 100000
    const int nnz = in_sizes[1];       // 600000

    void* yptr = nullptr;
    cudaGetSymbolAddress(&yptr, g_y);

    // zero scratch (e_feat float4s dominate: 640000 elems)
    k_zero<<<(640000 + 255) / 256, 256>>>();

    // degrees
    k_degree<<<(nnz + 255) / 256, 256>>>(ni, ei, nnz);
    k_inv<<<(NNODES + 255) / 256, 256>>>();

    // y = x @ conv_W ; out = x @ res_W + (res_b + conv_b)
    int gblocks = (M + 63) / 64;
    k_gemm<<<gblocks, 256>>>(x, conv_W, nullptr, nullptr, (float*)yptr, M);
    k_gemm<<<gblocks, 256>>>(x, res_W, res_b, conv_b, out, M);

    // scatter: node -> edge, then edge -> node (folding B^-1 and D^-1)
    int sblocks = (nnz + 7) / 8;
    k_scatter_edge<<<sblocks, 256>>>(ni, ei, nnz);
    k_scatter_node<<<sblocks, 256>>>(ni, ei, out, nnz);
}

// round 10
// speedup vs baseline: 1.1694x; 1.1694x over previous
#include <cuda_runtime.h>
#include <cstdint>
#include <cstddef>

#define NNODES 100000
#define NEDGES 20000
#define D 128

// ---- scratch (device globals: allocation-free) ----
__device__ __align__(16) float g_y[(size_t)NNODES * D];      // x @ conv_W
__device__ __align__(16) float g_efeat[(size_t)NEDGES * D];  // hyperedge accum
__device__ int   g_degn[NNODES];
__device__ int   g_dege[NEDGES];
__device__ float g_invn[NNODES];
__device__ float g_inve[NEDGES];

// ---- zero e_feat + degree counters ----
__global__ __launch_bounds__(256) void k_zero() {
    int i = blockIdx.x * blockDim.x + threadIdx.x;
    const int nef4 = (NEDGES * D) / 4;  // 640000 float4
    if (i < nef4) {
        ((float4*)g_efeat)[i] = make_float4(0.f, 0.f, 0.f, 0.f);
    }
    if (i < NNODES) g_degn[i] = 0;
    if (i < NEDGES) g_dege[i] = 0;
}

// ---- degree counts ----
__global__ __launch_bounds__(256) void k_degree(const int* __restrict__ ni,
                                                const int* __restrict__ ei, int nnz) {
    int i = blockIdx.x * blockDim.x + threadIdx.x;
    if (i < nnz) {
        atomicAdd(&g_degn[ni[i]], 1);
        atomicAdd(&g_dege[ei[i]], 1);
    }
}

// ---- 1/deg ----
__global__ __launch_bounds__(256) void k_inv() {
    int i = blockIdx.x * blockDim.x + threadIdx.x;
    if (i < NNODES) {
        int d = g_degn[i];
        g_invn[i] = d > 0 ? 1.0f / (float)d : 0.0f;
    }
    if (i < NEDGES) {
        int d = g_dege[i];
        g_inve[i] = d > 0 ? 1.0f / (float)d : 0.0f;
    }
}

// ---- packed f32x2 helpers (FFMA2 pipe: double-rate vs FFMA-3reg) ----
__device__ __forceinline__ unsigned long long pk2(float x, float y) {
    unsigned long long r;
    asm("mov.b64 %0, {%1, %2};" : "=l"(r) : "f"(x), "f"(y));
    return r;
}
__device__ __forceinline__ void fma2(unsigned long long& d,
                                     unsigned long long a,
                                     unsigned long long b) {
    asm("fma.rn.f32x2 %0, %1, %2, %0;" : "+l"(d) : "l"(a), "l"(b));
}
__device__ __forceinline__ float2 up2(unsigned long long v) {
    float2 r;
    asm("mov.b64 {%0, %1}, %2;" : "=f"(r.x), "=f"(r.y) : "l"(v));
    return r;
}

// ---- fused dual GEMM: C1 = A@B1 ; C2 = A@B2 + (bias1+bias2) ----
// Block tile 64x128, 256 threads, thread tile 8 rows x 4 cols x 2 matrices.
// Inner loop on fma.rn.f32x2 (FFMA2): 32 packed FMAs per k-step per thread.
__global__ __launch_bounds__(256) void k_gemm2(const float* __restrict__ A,
                                               const float* __restrict__ B1,
                                               const float* __restrict__ B2,
                                               const float* __restrict__ bias1,
                                               const float* __restrict__ bias2,
                                               float* __restrict__ C1,
                                               float* __restrict__ C2, int M) {
    __shared__ float As[8][64];    // [k][m] -> a-frag is LDS.128 broadcast
    __shared__ float Bs1[8][128];
    __shared__ float Bs2[8][128];

    const int t    = threadIdx.x;
    const int tx   = t & 31;       // n micro-tile (4 cols)
    const int ty   = t >> 5;       // m micro-tile (8 rows)
    const int row0 = blockIdx.x * 64;

    // A-load mapping: 64 rows x 8 k per iter; each thread one float2 along k
    const int tm  = t & 63;
    const int tk2 = (t >> 6) * 2;  // 0,2,4,6
    int arow = row0 + tm;
    if (arow >= M) arow = M - 1;   // clamp; epilogue guards writes
    const float* Aptr = A + (size_t)arow * D + tk2;

    // B-load mapping: 8 rows x 128; each thread one float4 from each W
    const int kb = t >> 5;
    const int nb = (t & 31) * 4;

    // packed accumulators: [row][colpair] for each matrix (0.0f|0.0f == 0ull)
    unsigned long long acc1[8][2], acc2[8][2];
#pragma unroll
    for (int i = 0; i < 8; i++) {
        acc1[i][0] = 0ull; acc1[i][1] = 0ull;
        acc2[i][0] = 0ull; acc2[i][1] = 0ull;
    }

    for (int kk = 0; kk < D; kk += 8) {
        float2 a2 = *(const float2*)(Aptr + kk);
        As[tk2][tm]     = a2.x;
        As[tk2 + 1][tm] = a2.y;
        *(float4*)&Bs1[kb][nb] = *(const float4*)&B1[(size_t)(kk + kb) * D + nb];
        *(float4*)&Bs2[kb][nb] = *(const float4*)&B2[(size_t)(kk + kb) * D + nb];
        __syncthreads();
#pragma unroll
        for (int k = 0; k < 8; k++) {
            float4 b1 = *(const float4*)&Bs1[k][tx * 4];
            float4 b2 = *(const float4*)&Bs2[k][tx * 4];
            unsigned long long pb1lo = pk2(b1.x, b1.y);
            unsigned long long pb1hi = pk2(b1.z, b1.w);
            unsigned long long pb2lo = pk2(b2.x, b2.y);
            unsigned long long pb2hi = pk2(b2.z, b2.w);
            float4 a0 = *(const float4*)&As[k][ty * 8];
            float4 a1 = *(const float4*)&As[k][ty * 8 + 4];
            float a[8] = {a0.x, a0.y, a0.z, a0.w, a1.x, a1.y, a1.z, a1.w};
#pragma unroll
            for (int i = 0; i < 8; i++) {
                unsigned long long ap = pk2(a[i], a[i]);
                fma2(acc1[i][0], ap, pb1lo);
                fma2(acc1[i][1], ap, pb1hi);
                fma2(acc2[i][0], ap, pb2lo);
                fma2(acc2[i][1], ap, pb2hi);
            }
        }
        __syncthreads();
    }

    float4 bias = make_float4(0.f, 0.f, 0.f, 0.f);
    {
        float4 ba = *(const float4*)&bias1[tx * 4];
        float4 bb = *(const float4*)&bias2[tx * 4];
        bias.x = ba.x + bb.x; bias.y = ba.y + bb.y;
        bias.z = ba.z + bb.z; bias.w = ba.w + bb.w;
    }
#pragma unroll
    for (int i = 0; i < 8; i++) {
        int row = row0 + ty * 8 + i;
        if (row < M) {
            float2 l0 = up2(acc1[i][0]);
            float2 l1 = up2(acc1[i][1]);
            *(float4*)&C1[(size_t)row * D + tx * 4] =
                make_float4(l0.x, l0.y, l1.x, l1.y);
            float2 m0 = up2(acc2[i][0]);
            float2 m1 = up2(acc2[i][1]);
            *(float4*)&C2[(size_t)row * D + tx * 4] =
                make_float4(m0.x + bias.x, m0.y + bias.y,
                            m1.x + bias.z, m1.y + bias.w);
        }
    }
}

__device__ __forceinline__ void red_add_v4(float* p, float4 v) {
    asm volatile("red.global.add.v4.f32 [%0], {%1, %2, %3, %4};"
                 :: "l"(p), "f"(v.x), "f"(v.y), "f"(v.z), "f"(v.w)
                 : "memory");
}

// ---- pass 1: e_feat[edge] += y[node]  (one warp per nz, float4/lane) ----
__global__ __launch_bounds__(256) void k_scatter_edge(const int* __restrict__ ni,
                                                      const int* __restrict__ ei, int nnz) {
    int w = blockIdx.x * 8 + (threadIdx.x >> 5);
    int lane = threadIdx.x & 31;
    if (w >= nnz) return;
    int node = __ldg(&ni[w]);
    int edge = __ldg(&ei[w]);
    float4 v = *(const float4*)&g_y[(size_t)node * D + lane * 4];
    red_add_v4(&g_efeat[(size_t)edge * D + lane * 4], v);
}

// ---- pass 2: out[node] += e_feat[edge] * inv_e[edge] * inv_n[node] ----
__global__ __launch_bounds__(256) void k_scatter_node(const int* __restrict__ ni,
                                                      const int* __restrict__ ei,
                                                      float* __restrict__ out, int nnz) {
    int w = blockIdx.x * 8 + (threadIdx.x >> 5);
    int lane = threadIdx.x & 31;
    if (w >= nnz) return;
    int node = __ldg(&ni[w]);
    int edge = __ldg(&ei[w]);
    float s = g_inve[edge] * g_invn[node];
    float4 v = *(const float4*)&g_efeat[(size_t)edge * D + lane * 4];
    v.x *= s; v.y *= s; v.z *= s; v.w *= s;
    red_add_v4(&out[(size_t)node * D + lane * 4], v);
}

extern "C" void kernel_launch(void* const* d_in, const int* in_sizes, int n_in,
                              void* d_out, int out_size) {
    const float* x      = (const float*)d_in[0];
    const int*   ni     = (const int*)d_in[1];
    const int*   ei     = (const int*)d_in[2];
    const float* conv_W = (const float*)d_in[3];
    const float* conv_b = (const float*)d_in[4];
    const float* res_W  = (const float*)d_in[5];
    const float* res_b  = (const float*)d_in[6];
    float* out = (float*)d_out;

    const int M   = in_sizes[0] / D;   // 100000
    const int nnz = in_sizes[1];       // 600000

    void* yptr = nullptr;
    cudaGetSymbolAddress(&yptr, g_y);

    // zero scratch (e_feat float4s dominate: 640000 elems)
    k_zero<<<(640000 + 255) / 256, 256>>>();

    // degrees
    k_degree<<<(nnz + 255) / 256, 256>>>(ni, ei, nnz);
    k_inv<<<(NNODES + 255) / 256, 256>>>();

    // fused: y = x @ conv_W ; out = x @ res_W + (res_b + conv_b)
    int gblocks = (M + 63) / 64;
    k_gemm2<<<gblocks, 256>>>(x, conv_W, res_W, res_b, conv_b,
                              (float*)yptr, out, M);

    // scatter: node -> edge, then edge -> node (folding B^-1 and D^-1)
    int sblocks = (nnz + 7) / 8;
    k_scatter_edge<<<sblocks, 256>>>(ni, ei, nnz);
    k_scatter_node<<<sblocks, 256>>>(ni, ei, out, nnz);
}

// round 11
// speedup vs baseline: 1.1697x; 1.0002x over previous
#include <cuda_runtime.h>
#include <cstdint>
#include <cstddef>

#define NNODES 100000
#define NEDGES 20000
#define D 128

// ---- scratch (device globals: allocation-free) ----
__device__ __align__(16) float g_y[(size_t)NNODES * D];      // x @ conv_W
__device__ __align__(16) float g_efeat[(size_t)NEDGES * D];  // hyperedge accum
__device__ int   g_degn[NNODES];
__device__ int   g_dege[NEDGES];
__device__ float g_invn[NNODES];
__device__ float g_inve[NEDGES];

// ---- zero e_feat + degree counters ----
__global__ __launch_bounds__(256) void k_zero() {
    int i = blockIdx.x * blockDim.x + threadIdx.x;
    const int nef4 = (NEDGES * D) / 4;  // 640000 float4
    if (i < nef4) {
        ((float4*)g_efeat)[i] = make_float4(0.f, 0.f, 0.f, 0.f);
    }
    if (i < NNODES) g_degn[i] = 0;
    if (i < NEDGES) g_dege[i] = 0;
}

// ---- degree counts ----
__global__ __launch_bounds__(256) void k_degree(const int* __restrict__ ni,
                                                const int* __restrict__ ei, int nnz) {
    int i = blockIdx.x * blockDim.x + threadIdx.x;
    if (i < nnz) {
        atomicAdd(&g_degn[ni[i]], 1);
        atomicAdd(&g_dege[ei[i]], 1);
    }
}

// ---- 1/deg ----
__global__ __launch_bounds__(256) void k_inv() {
    int i = blockIdx.x * blockDim.x + threadIdx.x;
    if (i < NNODES) {
        int d = g_degn[i];
        g_invn[i] = d > 0 ? 1.0f / (float)d : 0.0f;
    }
    if (i < NEDGES) {
        int d = g_dege[i];
        g_inve[i] = d > 0 ? 1.0f / (float)d : 0.0f;
    }
}

// ---- packed f32x2 helpers (FFMA2 pipe: double-rate vs FFMA-3reg) ----
__device__ __forceinline__ unsigned long long pk2(float x, float y) {
    unsigned long long r;
    asm("mov.b64 %0, {%1, %2};" : "=l"(r) : "f"(x), "f"(y));
    return r;
}
__device__ __forceinline__ void fma2(unsigned long long& d,
                                     unsigned long long a,
                                     unsigned long long b) {
    asm("fma.rn.f32x2 %0, %1, %2, %0;" : "+l"(d) : "l"(a), "l"(b));
}
__device__ __forceinline__ float2 up2(unsigned long long v) {
    float2 r;
    asm("mov.b64 {%0, %1}, %2;" : "=f"(r.x), "=f"(r.y) : "l"(v));
    return r;
}

// ---- fused dual GEMM: C1 = A@B1 ; C2 = A@B2 + (bias1+bias2) ----
// Block tile 64x128, 256 threads, thread tile 8 rows x 4 cols x 2 matrices.
// Inner loop on fma.rn.f32x2 (FFMA2): 32 packed FMAs per k-step per thread.
__global__ __launch_bounds__(256) void k_gemm2(const float* __restrict__ A,
                                               const float* __restrict__ B1,
                                               const float* __restrict__ B2,
                                               const float* __restrict__ bias1,
                                               const float* __restrict__ bias2,
                                               float* __restrict__ C1,
                                               float* __restrict__ C2, int M) {
    __shared__ float As[8][64];    // [k][m] -> a-frag is LDS.128 broadcast
    __shared__ float Bs1[8][128];
    __shared__ float Bs2[8][128];

    const int t    = threadIdx.x;
    const int tx   = t & 31;       // n micro-tile (4 cols)
    const int ty   = t >> 5;       // m micro-tile (8 rows)
    const int row0 = blockIdx.x * 64;

    // A-load mapping: 64 rows x 8 k per iter; each thread one float2 along k
    const int tm  = t & 63;
    const int tk2 = (t >> 6) * 2;  // 0,2,4,6
    int arow = row0 + tm;
    if (arow >= M) arow = M - 1;   // clamp; epilogue guards writes
    const float* Aptr = A + (size_t)arow * D + tk2;

    // B-load mapping: 8 rows x 128; each thread one float4 from each W
    const int kb = t >> 5;
    const int nb = (t & 31) * 4;

    // packed accumulators: [row][colpair] for each matrix (0.0f|0.0f == 0ull)
    unsigned long long acc1[8][2], acc2[8][2];
#pragma unroll
    for (int i = 0; i < 8; i++) {
        acc1[i][0] = 0ull; acc1[i][1] = 0ull;
        acc2[i][0] = 0ull; acc2[i][1] = 0ull;
    }

    for (int kk = 0; kk < D; kk += 8) {
        float2 a2 = *(const float2*)(Aptr + kk);
        As[tk2][tm]     = a2.x;
        As[tk2 + 1][tm] = a2.y;
        *(float4*)&Bs1[kb][nb] = *(const float4*)&B1[(size_t)(kk + kb) * D + nb];
        *(float4*)&Bs2[kb][nb] = *(const float4*)&B2[(size_t)(kk + kb) * D + nb];
        __syncthreads();
#pragma unroll
        for (int k = 0; k < 8; k++) {
            float4 b1 = *(const float4*)&Bs1[k][tx * 4];
            float4 b2 = *(const float4*)&Bs2[k][tx * 4];
            unsigned long long pb1lo = pk2(b1.x, b1.y);
            unsigned long long pb1hi = pk2(b1.z, b1.w);
            unsigned long long pb2lo = pk2(b2.x, b2.y);
            unsigned long long pb2hi = pk2(b2.z, b2.w);
            float4 a0 = *(const float4*)&As[k][ty * 8];
            float4 a1 = *(const float4*)&As[k][ty * 8 + 4];
            float a[8] = {a0.x, a0.y, a0.z, a0.w, a1.x, a1.y, a1.z, a1.w};
#pragma unroll
            for (int i = 0; i < 8; i++) {
                unsigned long long ap = pk2(a[i], a[i]);
                fma2(acc1[i][0], ap, pb1lo);
                fma2(acc1[i][1], ap, pb1hi);
                fma2(acc2[i][0], ap, pb2lo);
                fma2(acc2[i][1], ap, pb2hi);
            }
        }
        __syncthreads();
    }

    float4 bias = make_float4(0.f, 0.f, 0.f, 0.f);
    {
        float4 ba = *(const float4*)&bias1[tx * 4];
        float4 bb = *(const float4*)&bias2[tx * 4];
        bias.x = ba.x + bb.x; bias.y = ba.y + bb.y;
        bias.z = ba.z + bb.z; bias.w = ba.w + bb.w;
    }
#pragma unroll
    for (int i = 0; i < 8; i++) {
        int row = row0 + ty * 8 + i;
        if (row < M) {
            float2 l0 = up2(acc1[i][0]);
            float2 l1 = up2(acc1[i][1]);
            *(float4*)&C1[(size_t)row * D + tx * 4] =
                make_float4(l0.x, l0.y, l1.x, l1.y);
            float2 m0 = up2(acc2[i][0]);
            float2 m1 = up2(acc2[i][1]);
            *(float4*)&C2[(size_t)row * D + tx * 4] =
                make_float4(m0.x + bias.x, m0.y + bias.y,
                            m1.x + bias.z, m1.y + bias.w);
        }
    }
}

__device__ __forceinline__ void red_add_v4(float* p, float4 v) {
    asm volatile("red.global.add.v4.f32 [%0], {%1, %2, %3, %4};"
                 :: "l"(p), "f"(v.x), "f"(v.y), "f"(v.z), "f"(v.w)
                 : "memory");
}

// ---- pass 1: e_feat[edge] += y[node]  (one warp per nz, float4/lane) ----
__global__ __launch_bounds__(256) void k_scatter_edge(const int* __restrict__ ni,
                                                      const int* __restrict__ ei, int nnz) {
    int w = blockIdx.x * 8 + (threadIdx.x >> 5);
    int lane = threadIdx.x & 31;
    if (w >= nnz) return;
    int node = __ldg(&ni[w]);
    int edge = __ldg(&ei[w]);
    float4 v = *(const float4*)&g_y[(size_t)node * D + lane * 4];
    red_add_v4(&g_efeat[(size_t)edge * D + lane * 4], v);
}

// ---- pass 2: out[node] += e_feat[edge] * inv_e[edge] * inv_n[node] ----
__global__ __launch_bounds__(256) void k_scatter_node(const int* __restrict__ ni,
                                                      const int* __restrict__ ei,
                                                      float* __restrict__ out, int nnz) {
    int w = blockIdx.x * 8 + (threadIdx.x >> 5);
    int lane = threadIdx.x & 31;
    if (w >= nnz) return;
    int node = __ldg(&ni[w]);
    int edge = __ldg(&ei[w]);
    float s = g_inve[edge] * g_invn[node];
    float4 v = *(const float4*)&g_efeat[(size_t)edge * D + lane * 4];
    v.x *= s; v.y *= s; v.z *= s; v.w *= s;
    red_add_v4(&out[(size_t)node * D + lane * 4], v);
}

extern "C" void kernel_launch(void* const* d_in, const int* in_sizes, int n_in,
                              void* d_out, int out_size) {
    const float* x      = (const float*)d_in[0];
    const int*   ni     = (const int*)d_in[1];
    const int*   ei     = (const int*)d_in[2];
    const float* conv_W = (const float*)d_in[3];
    const float* conv_b = (const float*)d_in[4];
    const float* res_W  = (const float*)d_in[5];
    const float* res_b  = (const float*)d_in[6];
    float* out = (float*)d_out;

    const int M   = in_sizes[0] / D;   // 100000
    const int nnz = in_sizes[1];       // 600000

    void* yptr = nullptr;
    cudaGetSymbolAddress(&yptr, g_y);

    // zero scratch (e_feat float4s dominate: 640000 elems)
    k_zero<<<(640000 + 255) / 256, 256>>>();

    // degrees
    k_degree<<<(nnz + 255) / 256, 256>>>(ni, ei, nnz);
    k_inv<<<(NNODES + 255) / 256, 256>>>();

    // fused: y = x @ conv_W ; out = x @ res_W + (res_b + conv_b)
    int gblocks = (M + 63) / 64;
    k_gemm2<<<gblocks, 256>>>(x, conv_W, res_W, res_b, conv_b,
                              (float*)yptr, out, M);

    // scatter: node -> edge, then edge -> node (folding B^-1 and D^-1)
    int sblocks = (nnz + 7) / 8;
    k_scatter_edge<<<sblocks, 256>>>(ni, ei, nnz);
    k_scatter_node<<<sblocks, 256>>>(ni, ei, out, nnz);
}